// round 8
// baseline (speedup 1.0000x reference)
#include <cuda_runtime.h>
#include <cstdint>

#define B_  2
#define T_  2048
#define D_  2048
#define H_  32
#define HD_ 64
#define SCALE_ 0.125f   // 1/sqrt(64)

// ---------------- scratch (device globals: allocation-free) ----------------
__device__ float g_x [(size_t)B_ * T_ * D_];
__device__ float g_wq[(size_t)D_ * D_];
__device__ float g_wk[(size_t)D_ * D_];
__device__ float g_wv[(size_t)D_ * D_];
__device__ float g_wo[(size_t)D_ * D_];
__device__ float g_q [(size_t)B_ * H_ * T_ * HD_];
__device__ float g_k [(size_t)B_ * H_ * T_ * HD_];
__device__ float g_v [(size_t)B_ * H_ * T_ * HD_];
__device__ float g_ctx[(size_t)B_ * T_ * D_];

// ---------------- helpers ----------------
__device__ __forceinline__ float to_tf32(float x) {
    uint32_t u;
    asm("cvt.rna.tf32.f32 %0, %1;" : "=r"(u) : "f"(x));
    return __uint_as_float(u);
}

__device__ __forceinline__ void mma8(float* c, const uint32_t* a, const uint32_t* b) {
    asm volatile(
        "mma.sync.aligned.m16n8k8.row.col.f32.tf32.tf32.f32 "
        "{%0,%1,%2,%3},{%4,%5,%6,%7},{%8,%9},{%0,%1,%2,%3};\n"
        : "+f"(c[0]), "+f"(c[1]), "+f"(c[2]), "+f"(c[3])
        : "r"(a[0]), "r"(a[1]), "r"(a[2]), "r"(a[3]), "r"(b[0]), "r"(b[1]));
}

__device__ __forceinline__ void cp16(uint32_t saddr, const void* g) {
    asm volatile("cp.async.cg.shared.global [%0], [%1], 16;\n"
                 :: "r"(saddr), "l"(g) : "memory");
}
__device__ __forceinline__ void cp_commit() {
    asm volatile("cp.async.commit_group;\n" ::: "memory");
}
__device__ __forceinline__ void cp_wait0() {
    asm volatile("cp.async.wait_group 0;\n" ::: "memory");
}
__device__ __forceinline__ void cp_wait1() {
    asm volatile("cp.async.wait_group 1;\n" ::: "memory");
}

// ============================================================================
// Pre-round: out[i] = tf32_round(in[i]) (vectorized)
// ============================================================================
__global__ __launch_bounds__(256) void round_tf32_kernel(
    const float4* __restrict__ in, float4* __restrict__ out, int n4)
{
    int i = blockIdx.x * 256 + threadIdx.x;
    if (i < n4) {
        float4 v = in[i];
        v.x = to_tf32(v.x); v.y = to_tf32(v.y);
        v.z = to_tf32(v.z); v.w = to_tf32(v.w);
        out[i] = v;
    }
}

// ============================================================================
// TF32 GEMM: C[M,N] = A[M,K] @ W[N,K]^T + bias. A,W pre-rounded to tf32.
// 3-stage cp.async ring, k32 stages, wait_group 1 (2 stages in flight).
// Dynamic smem: 3 stages x (As[128][36] + Bs[128][36]) = 108 KB.
// MODE 0: C row-major [M,N]. MODE 1: headed scatter to [B,H,T,HD], tf32 store.
// Block tile 128x128, 8 warps (4x2), warp tile 32x64.
// ============================================================================
#define GEMM_STAGE_F (2 * 128 * 36)                 // floats per stage (A+B)
#define GEMM_SMEM_BYTES (3 * GEMM_STAGE_F * 4)      // 110592 bytes

template <int MODE>
__global__ __launch_bounds__(256) void gemm_tf32(
    const float* __restrict__ A, const float* __restrict__ W,
    const float* __restrict__ bias, float* __restrict__ C,
    int M, int N, int K)
{
    extern __shared__ float sm[];

    const int tid  = threadIdx.x;
    const int m0   = blockIdx.y * 128;
    const int n0   = blockIdx.x * 128;
    const int warp = tid >> 5, lane = tid & 31;
    const int wm   = warp >> 1;       // 0..3
    const int wn   = warp & 1;        // 0..1
    const int gid  = lane >> 2;       // 0..7
    const int tig  = lane & 3;        // 0..3

    float acc[2][8][4];
#pragma unroll
    for (int i = 0; i < 2; i++)
#pragma unroll
        for (int j = 0; j < 8; j++)
#pragma unroll
            for (int r = 0; r < 4; r++) acc[i][j][r] = 0.f;

    const int row_ld = tid >> 1;            // 0..127
    const int col_ld = (tid & 1) * 16;      // 0 or 16
    const float* ga0 = A + (size_t)(m0 + row_ld) * K + col_ld;
    const float* gb0 = W + (size_t)(n0 + row_ld) * K + col_ld;

    auto issue = [&](int kt, int s) {
        float* Asf = sm + (size_t)s * GEMM_STAGE_F;
        float* Bsf = Asf + 128 * 36;
        uint32_t sa = (uint32_t)__cvta_generic_to_shared(Asf + row_ld * 36 + col_ld);
        uint32_t sb = (uint32_t)__cvta_generic_to_shared(Bsf + row_ld * 36 + col_ld);
        const float* ga = ga0 + kt * 32;
        const float* gb = gb0 + kt * 32;
#pragma unroll
        for (int i = 0; i < 4; ++i) {
            cp16(sa + i * 16, ga + i * 4);
            cp16(sb + i * 16, gb + i * 4);
        }
    };

    const int KT = K >> 5;   // 32-wide stages (64 total)
    issue(0, 0); cp_commit();
    issue(1, 1); cp_commit();

    for (int kt = 0; kt < KT; ++kt) {
        const int buf = kt - (kt / 3) * 3;   // kt % 3
        if (kt + 1 < KT) cp_wait1(); else cp_wait0();
        __syncthreads();
        if (kt + 2 < KT) {
            int nb = kt + 2;
            issue(nb, nb - (nb / 3) * 3);
            cp_commit();
        }

        const float* As = sm + (size_t)buf * GEMM_STAGE_F;
        const float* Bs = As + 128 * 36;

#pragma unroll
        for (int ks = 0; ks < 4; ++ks) {
            const int k = ks * 8;
            uint32_t af[2][4];
#pragma unroll
            for (int mf = 0; mf < 2; ++mf) {
                int r = wm * 32 + mf * 16;
                af[mf][0] = __float_as_uint(As[(r + gid    ) * 36 + k + tig    ]);
                af[mf][1] = __float_as_uint(As[(r + gid + 8) * 36 + k + tig    ]);
                af[mf][2] = __float_as_uint(As[(r + gid    ) * 36 + k + tig + 4]);
                af[mf][3] = __float_as_uint(As[(r + gid + 8) * 36 + k + tig + 4]);
            }
            uint32_t bf[8][2];
#pragma unroll
            for (int nf = 0; nf < 8; ++nf) {
                int c = wn * 64 + nf * 8;
                bf[nf][0] = __float_as_uint(Bs[(c + gid) * 36 + k + tig    ]);
                bf[nf][1] = __float_as_uint(Bs[(c + gid) * 36 + k + tig + 4]);
            }
#pragma unroll
            for (int mf = 0; mf < 2; ++mf)
#pragma unroll
                for (int nf = 0; nf < 8; ++nf)
                    mma8(acc[mf][nf], af[mf], bf[nf]);
        }
    }

    // epilogue
#pragma unroll
    for (int mf = 0; mf < 2; ++mf) {
#pragma unroll
        for (int nf = 0; nf < 8; ++nf) {
            int col  = n0 + wn * 64 + nf * 8 + tig * 2;
            float b0 = bias[col], b1 = bias[col + 1];
            int row0 = m0 + wm * 32 + mf * 16 + gid;
            if (MODE == 0) {
                float2 v0 = make_float2(acc[mf][nf][0] + b0, acc[mf][nf][1] + b1);
                float2 v1 = make_float2(acc[mf][nf][2] + b0, acc[mf][nf][3] + b1);
                *(float2*)(C + (size_t)row0 * N + col)       = v0;
                *(float2*)(C + (size_t)(row0 + 8) * N + col) = v1;
            } else {
                // tf32-rounded store so consumers need no cvt
                float2 v0 = make_float2(to_tf32(acc[mf][nf][0] + b0), to_tf32(acc[mf][nf][1] + b1));
                float2 v1 = make_float2(to_tf32(acc[mf][nf][2] + b0), to_tf32(acc[mf][nf][3] + b1));
                int b  = row0 >> 11;
                int hh = col >> 6;
                size_t i0 = (((size_t)b * H_ + hh) * T_ + (row0 & 2047)) * HD_ + (col & 63);
                size_t i1 = (((size_t)b * H_ + hh) * T_ + ((row0 + 8) & 2047)) * HD_ + (col & 63);
                *(float2*)(C + i0) = v0;
                *(float2*)(C + i1) = v1;
            }
        }
    }
}

// ============================================================================
// Causal flash attention, TF32 mma. 8 warps (4 wm x 2 wn), Br=64, Bc=32, HD=64.
// Inputs pre-rounded tf32. Softmax: 4 threads/row (quad shuffles), interleaved
// columns c = q + 4j (conflict-free, stride 36 == 4 mod 32).
// Output ctx [B,T,D] stored tf32-rounded.  (unchanged from R7)
// ============================================================================
__global__ __launch_bounds__(256) void attn_flash(
    const float* __restrict__ Q, const float* __restrict__ K,
    const float* __restrict__ V, float* __restrict__ ctx)
{
    __shared__ float Qs[64][68];   // [q][hd]
    __shared__ float Ks[32][68];   // [kv][hd]
    __shared__ float Vs[64][36];   // [hd][kv]  (transposed)
    __shared__ float Ss[64][36];   // [q][kv]   S then P
    __shared__ float mrow[64], lrow[64], frow[64];

    const int tid  = threadIdx.x;
    const int warp = tid >> 5, lane = tid & 31;
    const int gid  = lane >> 2, tig = lane & 3;
    const int wm   = warp >> 1;        // 0..3 : 16 q-rows each
    const int wn   = warp & 1;         // 0..1
    const int qt   = blockIdx.x;       // query tile (64 rows)
    const int bh   = blockIdx.y;       // b*H + h

    const float* Qg = Q + (size_t)bh * T_ * HD_ + (size_t)qt * 64 * HD_;
    const float* Kg = K + (size_t)bh * T_ * HD_;
    const float* Vg = V + (size_t)bh * T_ * HD_;

    // load Q tile (already tf32)
    {
        int r = tid >> 2, c0 = (tid & 3) * 16;
#pragma unroll
        for (int i = 0; i < 4; ++i)
            *(float4*)&Qs[r][c0 + i * 4] = *(const float4*)(Qg + (size_t)r * HD_ + c0 + i * 4);
    }
    if (tid < 64) { mrow[tid] = -1e30f; lrow[tid] = 0.f; }

    float oacc[4][4];
#pragma unroll
    for (int i = 0; i < 4; i++)
#pragma unroll
        for (int j = 0; j < 4; j++) oacc[i][j] = 0.f;

    const int nkv = 2 * qt + 2;    // kv tiles of 32 up through the diagonal
    __syncthreads();

    for (int t = 0; t < nkv; ++t) {
        // ---- load K (direct) and V (transposed) tiles ----
        {
            int r = tid >> 3, c0 = (tid & 7) * 8;
#pragma unroll
            for (int i = 0; i < 2; ++i) {
                float4 kv = *(const float4*)(Kg + (size_t)(t * 32 + r) * HD_ + c0 + i * 4);
                *(float4*)&Ks[r][c0 + i * 4] = kv;
                float4 vv = *(const float4*)(Vg + (size_t)(t * 32 + r) * HD_ + c0 + i * 4);
                Vs[c0 + i * 4 + 0][r] = vv.x;
                Vs[c0 + i * 4 + 1][r] = vv.y;
                Vs[c0 + i * 4 + 2][r] = vv.z;
                Vs[c0 + i * 4 + 3][r] = vv.w;
            }
        }
        __syncthreads();

        // ---- S = Q @ K^T : warp tile rows [wm*16,+16), cols [wn*16,+16) ----
        float sacc[2][4];
#pragma unroll
        for (int i = 0; i < 2; i++)
#pragma unroll
            for (int j = 0; j < 4; j++) sacc[i][j] = 0.f;

#pragma unroll
        for (int ks = 0; ks < 8; ++ks) {
            const int k = ks * 8;
            uint32_t af[4];
            int r = wm * 16;
            af[0] = __float_as_uint(Qs[r + gid    ][k + tig    ]);
            af[1] = __float_as_uint(Qs[r + gid + 8][k + tig    ]);
            af[2] = __float_as_uint(Qs[r + gid    ][k + tig + 4]);
            af[3] = __float_as_uint(Qs[r + gid + 8][k + tig + 4]);
#pragma unroll
            for (int nf = 0; nf < 2; ++nf) {
                int c = wn * 16 + nf * 8;
                uint32_t bf[2];
                bf[0] = __float_as_uint(Ks[c + gid][k + tig    ]);
                bf[1] = __float_as_uint(Ks[c + gid][k + tig + 4]);
                mma8(sacc[nf], af, bf);
            }
        }
        // dump S tile to shared
#pragma unroll
        for (int nf = 0; nf < 2; ++nf) {
            int col = wn * 16 + nf * 8 + tig * 2;
            int row = wm * 16 + gid;
            Ss[row    ][col    ] = sacc[nf][0];
            Ss[row    ][col + 1] = sacc[nf][1];
            Ss[row + 8][col    ] = sacc[nf][2];
            Ss[row + 8][col + 1] = sacc[nf][3];
        }
        __syncthreads();

        // ---- online softmax: 4 threads per row, cols c = q + 4j ----
        {
            const int r = tid >> 2, q = tid & 3;
            const int grow = qt * 64 + r;
            float vb[8];
            float mx = -1e30f;
#pragma unroll
            for (int j = 0; j < 8; ++j) {
                int c  = q + 4 * j;
                int gc = t * 32 + c;
                float x = Ss[r][c] * SCALE_;
                if (gc > grow) x = -1e30f;
                vb[j] = x;
                mx = fmaxf(mx, x);
            }
            mx = fmaxf(mx, __shfl_xor_sync(0xffffffffu, mx, 1));
            mx = fmaxf(mx, __shfl_xor_sync(0xffffffffu, mx, 2));
            float mold = mrow[r];
            float mnew = fmaxf(mold, mx);
            float s = 0.f;
#pragma unroll
            for (int j = 0; j < 8; ++j) {
                float p = __expf(vb[j] - mnew);
                s += p;
                Ss[r][q + 4 * j] = to_tf32(p);
            }
            s += __shfl_xor_sync(0xffffffffu, s, 1);
            s += __shfl_xor_sync(0xffffffffu, s, 2);
            if (q == 0) {
                float f = __expf(mold - mnew);
                frow[r] = f;
                mrow[r] = mnew;
                lrow[r] = lrow[r] * f + s;
            }
        }
        __syncthreads();

        // ---- rescale O, then O += P @ V : warp rows [wm*16,+16), cols [wn*32,+32) ----
        {
            float f0 = frow[wm * 16 + gid];
            float f8 = frow[wm * 16 + gid + 8];
#pragma unroll
            for (int nf = 0; nf < 4; ++nf) {
                oacc[nf][0] *= f0; oacc[nf][1] *= f0;
                oacc[nf][2] *= f8; oacc[nf][3] *= f8;
            }
        }
#pragma unroll
        for (int ks = 0; ks < 4; ++ks) {
            const int k = ks * 8;
            uint32_t af[4];
            int r = wm * 16;
            af[0] = __float_as_uint(Ss[r + gid    ][k + tig    ]);
            af[1] = __float_as_uint(Ss[r + gid + 8][k + tig    ]);
            af[2] = __float_as_uint(Ss[r + gid    ][k + tig + 4]);
            af[3] = __float_as_uint(Ss[r + gid + 8][k + tig + 4]);
#pragma unroll
            for (int nf = 0; nf < 4; ++nf) {
                int c = wn * 32 + nf * 8;
                uint32_t bf[2];
                bf[0] = __float_as_uint(Vs[c + gid][k + tig    ]);
                bf[1] = __float_as_uint(Vs[c + gid][k + tig + 4]);
                mma8(oacc[nf], af, bf);
            }
        }
        __syncthreads();
    }

    // ---- write ctx [B,T,D], tf32-rounded ----
    {
        int r0 = wm * 16 + gid;
        float il0 = 1.f / lrow[r0];
        float il8 = 1.f / lrow[r0 + 8];
        int b = bh >> 5, h = bh & 31;
        size_t base = ((size_t)b * T_ + (size_t)qt * 64) * D_ + h * 64;
#pragma unroll
        for (int nf = 0; nf < 4; ++nf) {
            int col = wn * 32 + nf * 8 + tig * 2;
            float2 v0 = make_float2(to_tf32(oacc[nf][0] * il0), to_tf32(oacc[nf][1] * il0));
            float2 v1 = make_float2(to_tf32(oacc[nf][2] * il8), to_tf32(oacc[nf][3] * il8));
            *(float2*)(ctx + base + (size_t)r0 * D_ + col)       = v0;
            *(float2*)(ctx + base + (size_t)(r0 + 8) * D_ + col) = v1;
        }
    }
}

// ============================================================================
extern "C" void kernel_launch(void* const* d_in, const int* in_sizes, int n_in,
                              void* d_out, int out_size)
{
    (void)in_sizes; (void)n_in; (void)out_size;
    const float* X  = (const float*)d_in[0];
    const float* Wq = (const float*)d_in[1];
    const float* bq = (const float*)d_in[2];
    const float* Wk = (const float*)d_in[3];
    const float* bk = (const float*)d_in[4];
    const float* Wv = (const float*)d_in[5];
    const float* bv = (const float*)d_in[6];
    const float* Wo = (const float*)d_in[7];
    const float* bo = (const float*)d_in[8];
    float* out = (float*)d_out;

    float *x, *wq, *wk, *wv, *wo, *q, *k, *v, *ctx;
    cudaGetSymbolAddress((void**)&x,   g_x);
    cudaGetSymbolAddress((void**)&wq,  g_wq);
    cudaGetSymbolAddress((void**)&wk,  g_wk);
    cudaGetSymbolAddress((void**)&wv,  g_wv);
    cudaGetSymbolAddress((void**)&wo,  g_wo);
    cudaGetSymbolAddress((void**)&q,   g_q);
    cudaGetSymbolAddress((void**)&k,   g_k);
    cudaGetSymbolAddress((void**)&v,   g_v);
    cudaGetSymbolAddress((void**)&ctx, g_ctx);

    cudaFuncSetAttribute(gemm_tf32<0>, cudaFuncAttributeMaxDynamicSharedMemorySize, GEMM_SMEM_BYTES);
    cudaFuncSetAttribute(gemm_tf32<1>, cudaFuncAttributeMaxDynamicSharedMemorySize, GEMM_SMEM_BYTES);

    // pre-round activations + weights to tf32
    const int nx4 = B_ * T_ * D_ / 4;   // 2097152
    const int nw4 = D_ * D_ / 4;        // 1048576
    round_tf32_kernel<<<nx4 / 256, 256>>>((const float4*)X,  (float4*)x,  nx4);
    round_tf32_kernel<<<nw4 / 256, 256>>>((const float4*)Wq, (float4*)wq, nw4);
    round_tf32_kernel<<<nw4 / 256, 256>>>((const float4*)Wk, (float4*)wk, nw4);
    round_tf32_kernel<<<nw4 / 256, 256>>>((const float4*)Wv, (float4*)wv, nw4);
    round_tf32_kernel<<<nw4 / 256, 256>>>((const float4*)Wo, (float4*)wo, nw4);

    const int M = B_ * T_;   // 4096
    const int N = D_;        // 2048
    const int K = D_;        // 2048
    dim3 gg(N / 128, M / 128);   // 16 x 32

    gemm_tf32<1><<<gg, 256, GEMM_SMEM_BYTES>>>(x, wq, bq, q, M, N, K);
    gemm_tf32<1><<<gg, 256, GEMM_SMEM_BYTES>>>(x, wk, bk, k, M, N, K);
    gemm_tf32<1><<<gg, 256, GEMM_SMEM_BYTES>>>(x, wv, bv, v, M, N, K);

    attn_flash<<<dim3(T_ / 64, B_ * H_), 256>>>(q, k, v, ctx);

    gemm_tf32<0><<<gg, 256, GEMM_SMEM_BYTES>>>(ctx, wo, bo, out, M, N, K);
}

// round 9
// speedup vs baseline: 1.2457x; 1.2457x over previous
#include <cuda_runtime.h>
#include <cstdint>

#define B_  2
#define T_  2048
#define D_  2048
#define H_  32
#define HD_ 64
#define SCALE_ 0.125f   // 1/sqrt(64)

// ---------------- scratch (device globals: allocation-free) ----------------
__device__ float g_x [(size_t)B_ * T_ * D_];
__device__ float g_wq[(size_t)D_ * D_];
__device__ float g_wk[(size_t)D_ * D_];
__device__ float g_wv[(size_t)D_ * D_];
__device__ float g_wo[(size_t)D_ * D_];
__device__ float g_q [(size_t)B_ * H_ * T_ * HD_];
__device__ float g_k [(size_t)B_ * H_ * T_ * HD_];
__device__ float g_v [(size_t)B_ * H_ * T_ * HD_];
__device__ float g_ctx[(size_t)B_ * T_ * D_];

// ---------------- helpers ----------------
__device__ __forceinline__ float to_tf32(float x) {
    uint32_t u;
    asm("cvt.rna.tf32.f32 %0, %1;" : "=r"(u) : "f"(x));
    return __uint_as_float(u);
}

__device__ __forceinline__ void mma8(float* c, const uint32_t* a, const uint32_t* b) {
    asm volatile(
        "mma.sync.aligned.m16n8k8.row.col.f32.tf32.tf32.f32 "
        "{%0,%1,%2,%3},{%4,%5,%6,%7},{%8,%9},{%0,%1,%2,%3};\n"
        : "+f"(c[0]), "+f"(c[1]), "+f"(c[2]), "+f"(c[3])
        : "r"(a[0]), "r"(a[1]), "r"(a[2]), "r"(a[3]), "r"(b[0]), "r"(b[1]));
}

__device__ __forceinline__ void cp16(uint32_t saddr, const void* g) {
    asm volatile("cp.async.cg.shared.global [%0], [%1], 16;\n"
                 :: "r"(saddr), "l"(g) : "memory");
}
__device__ __forceinline__ void cp_commit() {
    asm volatile("cp.async.commit_group;\n" ::: "memory");
}
__device__ __forceinline__ void cp_wait0() {
    asm volatile("cp.async.wait_group 0;\n" ::: "memory");
}

// ============================================================================
// Pre-round: out[i] = tf32_round(in[i]) (vectorized)
// ============================================================================
__global__ __launch_bounds__(256) void round_tf32_kernel(
    const float4* __restrict__ in, float4* __restrict__ out, int n4)
{
    int i = blockIdx.x * 256 + threadIdx.x;
    if (i < n4) {
        float4 v = in[i];
        v.x = to_tf32(v.x); v.y = to_tf32(v.y);
        v.z = to_tf32(v.z); v.w = to_tf32(v.w);
        out[i] = v;
    }
}

// ============================================================================
// TF32 GEMM: C[M,N] = A[M,K] @ W[N,K]^T + bias. A,W pre-rounded to tf32.
// 2-stage cp.async ring, k32 stages, COALESCED pattern (4 lines/instr:
// row = tid>>3, col = (tid&7)*4). wait0 -> sync -> issue next -> compute.
// Dynamic smem: 2 stages x (As[128][36] + Bs[128][36]) = 73.7 KB.
// MODE 0: C row-major [M,N]. MODE 1: headed scatter to [B,H,T,HD], tf32 store.
// Block tile 128x128, 8 warps (4x2), warp tile 32x64.
// ============================================================================
#define GEMM_STAGE_F (2 * 128 * 36)                 // floats per stage (A+B)
#define GEMM_SMEM_BYTES (2 * GEMM_STAGE_F * 4)      // 73728 bytes

template <int MODE>
__global__ __launch_bounds__(256) void gemm_tf32(
    const float* __restrict__ A, const float* __restrict__ W,
    const float* __restrict__ bias, float* __restrict__ C,
    int M, int N, int K)
{
    extern __shared__ float sm[];

    const int tid  = threadIdx.x;
    const int m0   = blockIdx.y * 128;
    const int n0   = blockIdx.x * 128;
    const int warp = tid >> 5, lane = tid & 31;
    const int wm   = warp >> 1;       // 0..3
    const int wn   = warp & 1;        // 0..1
    const int gid  = lane >> 2;       // 0..7
    const int tig  = lane & 3;        // 0..3

    float acc[2][8][4];
#pragma unroll
    for (int i = 0; i < 2; i++)
#pragma unroll
        for (int j = 0; j < 8; j++)
#pragma unroll
            for (int r = 0; r < 4; r++) acc[i][j][r] = 0.f;

    const int row_ld = tid >> 3;            // 0..31 (warp: 4 consecutive rows)
    const int col_ld = (tid & 7) * 4;       // 0,4,...,28 (floats)
    const float* ga0 = A + (size_t)(m0 + row_ld) * K + col_ld;
    const float* gb0 = W + (size_t)(n0 + row_ld) * K + col_ld;

    auto issue = [&](int kt, int s) {
        float* Asf = sm + (size_t)s * GEMM_STAGE_F;
        float* Bsf = Asf + 128 * 36;
        const float* ga = ga0 + kt * 32;
        const float* gb = gb0 + kt * 32;
#pragma unroll
        for (int p = 0; p < 4; ++p) {
            uint32_t sa = (uint32_t)__cvta_generic_to_shared(Asf + (row_ld + p * 32) * 36 + col_ld);
            uint32_t sb = (uint32_t)__cvta_generic_to_shared(Bsf + (row_ld + p * 32) * 36 + col_ld);
            cp16(sa, ga + (size_t)p * 32 * K);
            cp16(sb, gb + (size_t)p * 32 * K);
        }
    };

    const int KT = K >> 5;   // 32-wide stages (64 total)
    issue(0, 0); cp_commit();

    for (int kt = 0; kt < KT; ++kt) {
        const int buf = kt & 1;
        cp_wait0();                 // stage kt arrived (only group pending)
        __syncthreads();            // all warps see it; all done reading buf^1
        if (kt + 1 < KT) { issue(kt + 1, buf ^ 1); cp_commit(); }

        const float* As = sm + (size_t)buf * GEMM_STAGE_F;
        const float* Bs = As + 128 * 36;

#pragma unroll
        for (int ks = 0; ks < 4; ++ks) {
            const int k = ks * 8;
            uint32_t af[2][4];
#pragma unroll
            for (int mf = 0; mf < 2; ++mf) {
                int r = wm * 32 + mf * 16;
                af[mf][0] = __float_as_uint(As[(r + gid    ) * 36 + k + tig    ]);
                af[mf][1] = __float_as_uint(As[(r + gid + 8) * 36 + k + tig    ]);
                af[mf][2] = __float_as_uint(As[(r + gid    ) * 36 + k + tig + 4]);
                af[mf][3] = __float_as_uint(As[(r + gid + 8) * 36 + k + tig + 4]);
            }
            uint32_t bf[8][2];
#pragma unroll
            for (int nf = 0; nf < 8; ++nf) {
                int c = wn * 64 + nf * 8;
                bf[nf][0] = __float_as_uint(Bs[(c + gid) * 36 + k + tig    ]);
                bf[nf][1] = __float_as_uint(Bs[(c + gid) * 36 + k + tig + 4]);
            }
#pragma unroll
            for (int mf = 0; mf < 2; ++mf)
#pragma unroll
                for (int nf = 0; nf < 8; ++nf)
                    mma8(acc[mf][nf], af[mf], bf[nf]);
        }
    }

    // epilogue
#pragma unroll
    for (int mf = 0; mf < 2; ++mf) {
#pragma unroll
        for (int nf = 0; nf < 8; ++nf) {
            int col  = n0 + wn * 64 + nf * 8 + tig * 2;
            float b0 = bias[col], b1 = bias[col + 1];
            int row0 = m0 + wm * 32 + mf * 16 + gid;
            if (MODE == 0) {
                float2 v0 = make_float2(acc[mf][nf][0] + b0, acc[mf][nf][1] + b1);
                float2 v1 = make_float2(acc[mf][nf][2] + b0, acc[mf][nf][3] + b1);
                *(float2*)(C + (size_t)row0 * N + col)       = v0;
                *(float2*)(C + (size_t)(row0 + 8) * N + col) = v1;
            } else {
                // tf32-rounded store so consumers need no cvt
                float2 v0 = make_float2(to_tf32(acc[mf][nf][0] + b0), to_tf32(acc[mf][nf][1] + b1));
                float2 v1 = make_float2(to_tf32(acc[mf][nf][2] + b0), to_tf32(acc[mf][nf][3] + b1));
                int b  = row0 >> 11;
                int hh = col >> 6;
                size_t i0 = (((size_t)b * H_ + hh) * T_ + (row0 & 2047)) * HD_ + (col & 63);
                size_t i1 = (((size_t)b * H_ + hh) * T_ + ((row0 + 8) & 2047)) * HD_ + (col & 63);
                *(float2*)(C + i0) = v0;
                *(float2*)(C + i1) = v1;
            }
        }
    }
}

// ============================================================================
// Causal flash attention, TF32 mma. 8 warps (4 wm x 2 wn), Br=64, Bc=32, HD=64.
// Inputs pre-rounded tf32. Softmax: 4 threads/row (quad shuffles), interleaved
// columns c = q + 4j (conflict-free, stride 36 == 4 mod 32).
// Output ctx [B,T,D] stored tf32-rounded.  (unchanged from R7/R8)
// ============================================================================
__global__ __launch_bounds__(256) void attn_flash(
    const float* __restrict__ Q, const float* __restrict__ K,
    const float* __restrict__ V, float* __restrict__ ctx)
{
    __shared__ float Qs[64][68];   // [q][hd]
    __shared__ float Ks[32][68];   // [kv][hd]
    __shared__ float Vs[64][36];   // [hd][kv]  (transposed)
    __shared__ float Ss[64][36];   // [q][kv]   S then P
    __shared__ float mrow[64], lrow[64], frow[64];

    const int tid  = threadIdx.x;
    const int warp = tid >> 5, lane = tid & 31;
    const int gid  = lane >> 2, tig = lane & 3;
    const int wm   = warp >> 1;        // 0..3 : 16 q-rows each
    const int wn   = warp & 1;         // 0..1
    const int qt   = blockIdx.x;       // query tile (64 rows)
    const int bh   = blockIdx.y;       // b*H + h

    const float* Qg = Q + (size_t)bh * T_ * HD_ + (size_t)qt * 64 * HD_;
    const float* Kg = K + (size_t)bh * T_ * HD_;
    const float* Vg = V + (size_t)bh * T_ * HD_;

    // load Q tile (already tf32)
    {
        int r = tid >> 2, c0 = (tid & 3) * 16;
#pragma unroll
        for (int i = 0; i < 4; ++i)
            *(float4*)&Qs[r][c0 + i * 4] = *(const float4*)(Qg + (size_t)r * HD_ + c0 + i * 4);
    }
    if (tid < 64) { mrow[tid] = -1e30f; lrow[tid] = 0.f; }

    float oacc[4][4];
#pragma unroll
    for (int i = 0; i < 4; i++)
#pragma unroll
        for (int j = 0; j < 4; j++) oacc[i][j] = 0.f;

    const int nkv = 2 * qt + 2;    // kv tiles of 32 up through the diagonal
    __syncthreads();

    for (int t = 0; t < nkv; ++t) {
        // ---- load K (direct) and V (transposed) tiles ----
        {
            int r = tid >> 3, c0 = (tid & 7) * 8;
#pragma unroll
            for (int i = 0; i < 2; ++i) {
                float4 kv = *(const float4*)(Kg + (size_t)(t * 32 + r) * HD_ + c0 + i * 4);
                *(float4*)&Ks[r][c0 + i * 4] = kv;
                float4 vv = *(const float4*)(Vg + (size_t)(t * 32 + r) * HD_ + c0 + i * 4);
                Vs[c0 + i * 4 + 0][r] = vv.x;
                Vs[c0 + i * 4 + 1][r] = vv.y;
                Vs[c0 + i * 4 + 2][r] = vv.z;
                Vs[c0 + i * 4 + 3][r] = vv.w;
            }
        }
        __syncthreads();

        // ---- S = Q @ K^T : warp tile rows [wm*16,+16), cols [wn*16,+16) ----
        float sacc[2][4];
#pragma unroll
        for (int i = 0; i < 2; i++)
#pragma unroll
            for (int j = 0; j < 4; j++) sacc[i][j] = 0.f;

#pragma unroll
        for (int ks = 0; ks < 8; ++ks) {
            const int k = ks * 8;
            uint32_t af[4];
            int r = wm * 16;
            af[0] = __float_as_uint(Qs[r + gid    ][k + tig    ]);
            af[1] = __float_as_uint(Qs[r + gid + 8][k + tig    ]);
            af[2] = __float_as_uint(Qs[r + gid    ][k + tig + 4]);
            af[3] = __float_as_uint(Qs[r + gid + 8][k + tig + 4]);
#pragma unroll
            for (int nf = 0; nf < 2; ++nf) {
                int c = wn * 16 + nf * 8;
                uint32_t bf[2];
                bf[0] = __float_as_uint(Ks[c + gid][k + tig    ]);
                bf[1] = __float_as_uint(Ks[c + gid][k + tig + 4]);
                mma8(sacc[nf], af, bf);
            }
        }
        // dump S tile to shared
#pragma unroll
        for (int nf = 0; nf < 2; ++nf) {
            int col = wn * 16 + nf * 8 + tig * 2;
            int row = wm * 16 + gid;
            Ss[row    ][col    ] = sacc[nf][0];
            Ss[row    ][col + 1] = sacc[nf][1];
            Ss[row + 8][col    ] = sacc[nf][2];
            Ss[row + 8][col + 1] = sacc[nf][3];
        }
        __syncthreads();

        // ---- online softmax: 4 threads per row, cols c = q + 4j ----
        {
            const int r = tid >> 2, q = tid & 3;
            const int grow = qt * 64 + r;
            float vb[8];
            float mx = -1e30f;
#pragma unroll
            for (int j = 0; j < 8; ++j) {
                int c  = q + 4 * j;
                int gc = t * 32 + c;
                float x = Ss[r][c] * SCALE_;
                if (gc > grow) x = -1e30f;
                vb[j] = x;
                mx = fmaxf(mx, x);
            }
            mx = fmaxf(mx, __shfl_xor_sync(0xffffffffu, mx, 1));
            mx = fmaxf(mx, __shfl_xor_sync(0xffffffffu, mx, 2));
            float mold = mrow[r];
            float mnew = fmaxf(mold, mx);
            float s = 0.f;
#pragma unroll
            for (int j = 0; j < 8; ++j) {
                float p = __expf(vb[j] - mnew);
                s += p;
                Ss[r][q + 4 * j] = to_tf32(p);
            }
            s += __shfl_xor_sync(0xffffffffu, s, 1);
            s += __shfl_xor_sync(0xffffffffu, s, 2);
            if (q == 0) {
                float f = __expf(mold - mnew);
                frow[r] = f;
                mrow[r] = mnew;
                lrow[r] = lrow[r] * f + s;
            }
        }
        __syncthreads();

        // ---- rescale O, then O += P @ V : warp rows [wm*16,+16), cols [wn*32,+32) ----
        {
            float f0 = frow[wm * 16 + gid];
            float f8 = frow[wm * 16 + gid + 8];
#pragma unroll
            for (int nf = 0; nf < 4; ++nf) {
                oacc[nf][0] *= f0; oacc[nf][1] *= f0;
                oacc[nf][2] *= f8; oacc[nf][3] *= f8;
            }
        }
#pragma unroll
        for (int ks = 0; ks < 4; ++ks) {
            const int k = ks * 8;
            uint32_t af[4];
            int r = wm * 16;
            af[0] = __float_as_uint(Ss[r + gid    ][k + tig    ]);
            af[1] = __float_as_uint(Ss[r + gid + 8][k + tig    ]);
            af[2] = __float_as_uint(Ss[r + gid    ][k + tig + 4]);
            af[3] = __float_as_uint(Ss[r + gid + 8][k + tig + 4]);
#pragma unroll
            for (int nf = 0; nf < 4; ++nf) {
                int c = wn * 32 + nf * 8;
                uint32_t bf[2];
                bf[0] = __float_as_uint(Vs[c + gid][k + tig    ]);
                bf[1] = __float_as_uint(Vs[c + gid][k + tig + 4]);
                mma8(oacc[nf], af, bf);
            }
        }
        __syncthreads();
    }

    // ---- write ctx [B,T,D], tf32-rounded ----
    {
        int r0 = wm * 16 + gid;
        float il0 = 1.f / lrow[r0];
        float il8 = 1.f / lrow[r0 + 8];
        int b = bh >> 5, h = bh & 31;
        size_t base = ((size_t)b * T_ + (size_t)qt * 64) * D_ + h * 64;
#pragma unroll
        for (int nf = 0; nf < 4; ++nf) {
            int col = wn * 32 + nf * 8 + tig * 2;
            float2 v0 = make_float2(to_tf32(oacc[nf][0] * il0), to_tf32(oacc[nf][1] * il0));
            float2 v1 = make_float2(to_tf32(oacc[nf][2] * il8), to_tf32(oacc[nf][3] * il8));
            *(float2*)(ctx + base + (size_t)r0 * D_ + col)       = v0;
            *(float2*)(ctx + base + (size_t)(r0 + 8) * D_ + col) = v1;
        }
    }
}

// ============================================================================
extern "C" void kernel_launch(void* const* d_in, const int* in_sizes, int n_in,
                              void* d_out, int out_size)
{
    (void)in_sizes; (void)n_in; (void)out_size;
    const float* X  = (const float*)d_in[0];
    const float* Wq = (const float*)d_in[1];
    const float* bq = (const float*)d_in[2];
    const float* Wk = (const float*)d_in[3];
    const float* bk = (const float*)d_in[4];
    const float* Wv = (const float*)d_in[5];
    const float* bv = (const float*)d_in[6];
    const float* Wo = (const float*)d_in[7];
    const float* bo = (const float*)d_in[8];
    float* out = (float*)d_out;

    float *x, *wq, *wk, *wv, *wo, *q, *k, *v, *ctx;
    cudaGetSymbolAddress((void**)&x,   g_x);
    cudaGetSymbolAddress((void**)&wq,  g_wq);
    cudaGetSymbolAddress((void**)&wk,  g_wk);
    cudaGetSymbolAddress((void**)&wv,  g_wv);
    cudaGetSymbolAddress((void**)&wo,  g_wo);
    cudaGetSymbolAddress((void**)&q,   g_q);
    cudaGetSymbolAddress((void**)&k,   g_k);
    cudaGetSymbolAddress((void**)&v,   g_v);
    cudaGetSymbolAddress((void**)&ctx, g_ctx);

    cudaFuncSetAttribute(gemm_tf32<0>, cudaFuncAttributeMaxDynamicSharedMemorySize, GEMM_SMEM_BYTES);
    cudaFuncSetAttribute(gemm_tf32<1>, cudaFuncAttributeMaxDynamicSharedMemorySize, GEMM_SMEM_BYTES);

    // pre-round activations + weights to tf32
    const int nx4 = B_ * T_ * D_ / 4;   // 2097152
    const int nw4 = D_ * D_ / 4;        // 1048576
    round_tf32_kernel<<<nx4 / 256, 256>>>((const float4*)X,  (float4*)x,  nx4);
    round_tf32_kernel<<<nw4 / 256, 256>>>((const float4*)Wq, (float4*)wq, nw4);
    round_tf32_kernel<<<nw4 / 256, 256>>>((const float4*)Wk, (float4*)wk, nw4);
    round_tf32_kernel<<<nw4 / 256, 256>>>((const float4*)Wv, (float4*)wv, nw4);
    round_tf32_kernel<<<nw4 / 256, 256>>>((const float4*)Wo, (float4*)wo, nw4);

    const int M = B_ * T_;   // 4096
    const int N = D_;        // 2048
    const int K = D_;        // 2048
    dim3 gg(N / 128, M / 128);   // 16 x 32

    gemm_tf32<1><<<gg, 256, GEMM_SMEM_BYTES>>>(x, wq, bq, q, M, N, K);
    gemm_tf32<1><<<gg, 256, GEMM_SMEM_BYTES>>>(x, wk, bk, k, M, N, K);
    gemm_tf32<1><<<gg, 256, GEMM_SMEM_BYTES>>>(x, wv, bv, v, M, N, K);

    attn_flash<<<dim3(T_ / 64, B_ * H_), 256>>>(q, k, v, ctx);

    gemm_tf32<0><<<gg, 256, GEMM_SMEM_BYTES>>>(ctx, wo, bo, out, M, N, K);
}

// round 10
// speedup vs baseline: 1.4546x; 1.1677x over previous
#include <cuda_runtime.h>
#include <cstdint>

#define B_  2
#define T_  2048
#define D_  2048
#define H_  32
#define HD_ 64
#define SCALE_ 0.125f   // 1/sqrt(64)

// ---------------- scratch (device globals: allocation-free) ----------------
__device__ float g_x [(size_t)B_ * T_ * D_];
__device__ float g_wq[(size_t)D_ * D_];
__device__ float g_wk[(size_t)D_ * D_];
__device__ float g_wv[(size_t)D_ * D_];
__device__ float g_wo[(size_t)D_ * D_];
__device__ float g_q [(size_t)B_ * H_ * T_ * HD_];
__device__ float g_k [(size_t)B_ * H_ * T_ * HD_];
__device__ float g_v [(size_t)B_ * H_ * T_ * HD_];
__device__ float g_ctx[(size_t)B_ * T_ * D_];

// ---------------- helpers ----------------
__device__ __forceinline__ float to_tf32(float x) {
    uint32_t u;
    asm("cvt.rna.tf32.f32 %0, %1;" : "=r"(u) : "f"(x));
    return __uint_as_float(u);
}

__device__ __forceinline__ void mma8(float* c, const uint32_t* a, const uint32_t* b) {
    asm volatile(
        "mma.sync.aligned.m16n8k8.row.col.f32.tf32.tf32.f32 "
        "{%0,%1,%2,%3},{%4,%5,%6,%7},{%8,%9},{%0,%1,%2,%3};\n"
        : "+f"(c[0]), "+f"(c[1]), "+f"(c[2]), "+f"(c[3])
        : "r"(a[0]), "r"(a[1]), "r"(a[2]), "r"(a[3]), "r"(b[0]), "r"(b[1]));
}

__device__ __forceinline__ void cp16(uint32_t saddr, const void* g) {
    asm volatile("cp.async.cg.shared.global [%0], [%1], 16;\n"
                 :: "r"(saddr), "l"(g) : "memory");
}
__device__ __forceinline__ void cp_commit() {
    asm volatile("cp.async.commit_group;\n" ::: "memory");
}
__device__ __forceinline__ void cp_wait0() {
    asm volatile("cp.async.wait_group 0;\n" ::: "memory");
}

// ============================================================================
// Pre-round: out[i] = tf32_round(in[i]) (vectorized)
// ============================================================================
__global__ __launch_bounds__(256) void round_tf32_kernel(
    const float4* __restrict__ in, float4* __restrict__ out, int n4)
{
    int i = blockIdx.x * 256 + threadIdx.x;
    if (i < n4) {
        float4 v = in[i];
        v.x = to_tf32(v.x); v.y = to_tf32(v.y);
        v.z = to_tf32(v.z); v.w = to_tf32(v.w);
        out[i] = v;
    }
}

// ============================================================================
// TF32 GEMM (unchanged from R9): 2-stage cp.async ring, k32 stages, coalesced.
// ============================================================================
#define GEMM_STAGE_F (2 * 128 * 36)
#define GEMM_SMEM_BYTES (2 * GEMM_STAGE_F * 4)      // 73728 bytes

template <int MODE>
__global__ __launch_bounds__(256) void gemm_tf32(
    const float* __restrict__ A, const float* __restrict__ W,
    const float* __restrict__ bias, float* __restrict__ C,
    int M, int N, int K)
{
    extern __shared__ float sm[];

    const int tid  = threadIdx.x;
    const int m0   = blockIdx.y * 128;
    const int n0   = blockIdx.x * 128;
    const int warp = tid >> 5, lane = tid & 31;
    const int wm   = warp >> 1;
    const int wn   = warp & 1;
    const int gid  = lane >> 2;
    const int tig  = lane & 3;

    float acc[2][8][4];
#pragma unroll
    for (int i = 0; i < 2; i++)
#pragma unroll
        for (int j = 0; j < 8; j++)
#pragma unroll
            for (int r = 0; r < 4; r++) acc[i][j][r] = 0.f;

    const int row_ld = tid >> 3;
    const int col_ld = (tid & 7) * 4;
    const float* ga0 = A + (size_t)(m0 + row_ld) * K + col_ld;
    const float* gb0 = W + (size_t)(n0 + row_ld) * K + col_ld;

    auto issue = [&](int kt, int s) {
        float* Asf = sm + (size_t)s * GEMM_STAGE_F;
        float* Bsf = Asf + 128 * 36;
        const float* ga = ga0 + kt * 32;
        const float* gb = gb0 + kt * 32;
#pragma unroll
        for (int p = 0; p < 4; ++p) {
            uint32_t sa = (uint32_t)__cvta_generic_to_shared(Asf + (row_ld + p * 32) * 36 + col_ld);
            uint32_t sb = (uint32_t)__cvta_generic_to_shared(Bsf + (row_ld + p * 32) * 36 + col_ld);
            cp16(sa, ga + (size_t)p * 32 * K);
            cp16(sb, gb + (size_t)p * 32 * K);
        }
    };

    const int KT = K >> 5;
    issue(0, 0); cp_commit();

    for (int kt = 0; kt < KT; ++kt) {
        const int buf = kt & 1;
        cp_wait0();
        __syncthreads();
        if (kt + 1 < KT) { issue(kt + 1, buf ^ 1); cp_commit(); }

        const float* As = sm + (size_t)buf * GEMM_STAGE_F;
        const float* Bs = As + 128 * 36;

#pragma unroll
        for (int ks = 0; ks < 4; ++ks) {
            const int k = ks * 8;
            uint32_t af[2][4];
#pragma unroll
            for (int mf = 0; mf < 2; ++mf) {
                int r = wm * 32 + mf * 16;
                af[mf][0] = __float_as_uint(As[(r + gid    ) * 36 + k + tig    ]);
                af[mf][1] = __float_as_uint(As[(r + gid + 8) * 36 + k + tig    ]);
                af[mf][2] = __float_as_uint(As[(r + gid    ) * 36 + k + tig + 4]);
                af[mf][3] = __float_as_uint(As[(r + gid + 8) * 36 + k + tig + 4]);
            }
            uint32_t bf[8][2];
#pragma unroll
            for (int nf = 0; nf < 8; ++nf) {
                int c = wn * 64 + nf * 8;
                bf[nf][0] = __float_as_uint(Bs[(c + gid) * 36 + k + tig    ]);
                bf[nf][1] = __float_as_uint(Bs[(c + gid) * 36 + k + tig + 4]);
            }
#pragma unroll
            for (int mf = 0; mf < 2; ++mf)
#pragma unroll
                for (int nf = 0; nf < 8; ++nf)
                    mma8(acc[mf][nf], af[mf], bf[nf]);
        }
    }

#pragma unroll
    for (int mf = 0; mf < 2; ++mf) {
#pragma unroll
        for (int nf = 0; nf < 8; ++nf) {
            int col  = n0 + wn * 64 + nf * 8 + tig * 2;
            float b0 = bias[col], b1 = bias[col + 1];
            int row0 = m0 + wm * 32 + mf * 16 + gid;
            if (MODE == 0) {
                float2 v0 = make_float2(acc[mf][nf][0] + b0, acc[mf][nf][1] + b1);
                float2 v1 = make_float2(acc[mf][nf][2] + b0, acc[mf][nf][3] + b1);
                *(float2*)(C + (size_t)row0 * N + col)       = v0;
                *(float2*)(C + (size_t)(row0 + 8) * N + col) = v1;
            } else {
                float2 v0 = make_float2(to_tf32(acc[mf][nf][0] + b0), to_tf32(acc[mf][nf][1] + b1));
                float2 v1 = make_float2(to_tf32(acc[mf][nf][2] + b0), to_tf32(acc[mf][nf][3] + b1));
                int b  = row0 >> 11;
                int hh = col >> 6;
                size_t i0 = (((size_t)b * H_ + hh) * T_ + (row0 & 2047)) * HD_ + (col & 63);
                size_t i1 = (((size_t)b * H_ + hh) * T_ + ((row0 + 8) & 2047)) * HD_ + (col & 63);
                *(float2*)(C + i0) = v0;
                *(float2*)(C + i1) = v1;
            }
        }
    }
}

// ============================================================================
// Causal flash attention v3: Br=64, Bc=64, HD=64, 8 warps (4 wm x 2 wn).
// cp.async double-buffered K/V (V untransposed, stride 72: B-fragment reads
// Vs[k+tig][c+gid] hit 32 distinct banks). 3 barriers per 64-KV tile.
// Softmax 4 threads/row x 16 cols. Mask only on the diagonal tile.
// Dynamic smem (floats): Qs 64x68 | Ss 64x68 | Ks 2x64x68 | Vs 2x64x72.
// ============================================================================
#define AT_QS   0
#define AT_SS   (64 * 68)
#define AT_KS   (2 * 64 * 68)
#define AT_VS   (4 * 64 * 68)
#define AT_KSTG (64 * 68)
#define AT_VSTG (64 * 72)
#define ATTN_SMEM_F (4 * 64 * 68 + 2 * 64 * 72)
#define ATTN_SMEM_BYTES (ATTN_SMEM_F * 4)           // 106496 bytes

__global__ __launch_bounds__(256) void attn_flash(
    const float* __restrict__ Q, const float* __restrict__ K,
    const float* __restrict__ V, float* __restrict__ ctx)
{
    extern __shared__ float sm[];
    float* Qs = sm + AT_QS;     // [64][68]
    float* Ss = sm + AT_SS;     // [64][68]
    float* Ks = sm + AT_KS;     // 2 x [64][68]
    float* Vs = sm + AT_VS;     // 2 x [64][72]  (row = kv, col = hd)
    __shared__ float mrow[64], lrow[64], frow[64];

    const int tid  = threadIdx.x;
    const int warp = tid >> 5, lane = tid & 31;
    const int gid  = lane >> 2, tig = lane & 3;
    const int wm   = warp >> 1;        // 0..3 : 16 q-rows each
    const int wn   = warp & 1;         // 0..1 : 32 kv-cols / 32 hd-cols each
    const int qt   = blockIdx.x;       // query tile (64 rows)
    const int bh   = blockIdx.y;       // b*H + h

    const float* Qg = Q + (size_t)bh * T_ * HD_ + (size_t)qt * 64 * HD_;
    const float* Kg = K + (size_t)bh * T_ * HD_;
    const float* Vg = V + (size_t)bh * T_ * HD_;

    // load Q tile (already tf32), coalesced: consecutive float4 indices
    {
#pragma unroll
        for (int i = 0; i < 4; ++i) {
            int f = tid + 256 * i;            // float4 index 0..1023
            int r = f >> 4, c = (f & 15) * 4;
            *(float4*)(Qs + r * 68 + c) = *(const float4*)(Qg + (size_t)r * HD_ + c);
        }
    }
    if (tid < 64) { mrow[tid] = -1e30f; lrow[tid] = 0.f; }

    auto issue_kv = [&](int t, int s) {
        const float* Kt = Kg + (size_t)t * 64 * HD_;
        const float* Vt = Vg + (size_t)t * 64 * HD_;
        float* Kd = Ks + (size_t)s * AT_KSTG;
        float* Vd = Vs + (size_t)s * AT_VSTG;
#pragma unroll
        for (int i = 0; i < 4; ++i) {
            int f = tid + 256 * i;            // float4 index 0..1023
            int r = f >> 4, c = (f & 15) * 4;
            cp16((uint32_t)__cvta_generic_to_shared(Kd + r * 68 + c), Kt + (size_t)r * HD_ + c);
            cp16((uint32_t)__cvta_generic_to_shared(Vd + r * 72 + c), Vt + (size_t)r * HD_ + c);
        }
    };

    float oacc[4][4];
#pragma unroll
    for (int i = 0; i < 4; i++)
#pragma unroll
        for (int j = 0; j < 4; j++) oacc[i][j] = 0.f;

    const int nkv = qt + 1;    // 64-wide kv tiles through the diagonal
    issue_kv(0, 0); cp_commit();

    for (int t = 0; t < nkv; ++t) {
        const int buf = t & 1;
        cp_wait0();
        __syncthreads();                       // K/V tile t ready; Ss free
        if (t + 1 < nkv) { issue_kv(t + 1, buf ^ 1); cp_commit(); }

        const float* Kb = Ks + (size_t)buf * AT_KSTG;
        const float* Vb = Vs + (size_t)buf * AT_VSTG;

        // ---- S = Q @ K^T : warp rows [wm*16,+16), cols [wn*32,+32) ----
        float sacc[4][4];
#pragma unroll
        for (int i = 0; i < 4; i++)
#pragma unroll
            for (int j = 0; j < 4; j++) sacc[i][j] = 0.f;

#pragma unroll
        for (int ks = 0; ks < 8; ++ks) {
            const int k = ks * 8;
            uint32_t af[4];
            int r = wm * 16;
            af[0] = __float_as_uint(Qs[(r + gid    ) * 68 + k + tig    ]);
            af[1] = __float_as_uint(Qs[(r + gid + 8) * 68 + k + tig    ]);
            af[2] = __float_as_uint(Qs[(r + gid    ) * 68 + k + tig + 4]);
            af[3] = __float_as_uint(Qs[(r + gid + 8) * 68 + k + tig + 4]);
#pragma unroll
            for (int nf = 0; nf < 4; ++nf) {
                int c = wn * 32 + nf * 8;
                uint32_t bf[2];
                bf[0] = __float_as_uint(Kb[(c + gid) * 68 + k + tig    ]);
                bf[1] = __float_as_uint(Kb[(c + gid) * 68 + k + tig + 4]);
                mma8(sacc[nf], af, bf);
            }
        }
        // dump S tile to shared
#pragma unroll
        for (int nf = 0; nf < 4; ++nf) {
            int col = wn * 32 + nf * 8 + tig * 2;
            int row = wm * 16 + gid;
            Ss[(row    ) * 68 + col    ] = sacc[nf][0];
            Ss[(row    ) * 68 + col + 1] = sacc[nf][1];
            Ss[(row + 8) * 68 + col    ] = sacc[nf][2];
            Ss[(row + 8) * 68 + col + 1] = sacc[nf][3];
        }
        __syncthreads();

        // ---- online softmax: 4 threads/row, 16 cols each (c = q + 4j) ----
        {
            const int r = tid >> 2, q = tid & 3;
            float vb[16];
            float mx = -1e30f;
            if (t == qt) {
                const int grow = qt * 64 + (tid >> 2);
#pragma unroll
                for (int j = 0; j < 16; ++j) {
                    int c  = q + 4 * j;
                    float x = Ss[r * 68 + c] * SCALE_;
                    if (t * 64 + c > grow) x = -1e30f;
                    vb[j] = x;
                    mx = fmaxf(mx, x);
                }
            } else {
#pragma unroll
                for (int j = 0; j < 16; ++j) {
                    float x = Ss[r * 68 + q + 4 * j] * SCALE_;
                    vb[j] = x;
                    mx = fmaxf(mx, x);
                }
            }
            mx = fmaxf(mx, __shfl_xor_sync(0xffffffffu, mx, 1));
            mx = fmaxf(mx, __shfl_xor_sync(0xffffffffu, mx, 2));
            float mold = mrow[r];
            float mnew = fmaxf(mold, mx);
            float s = 0.f;
#pragma unroll
            for (int j = 0; j < 16; ++j) {
                float p = __expf(vb[j] - mnew);
                s += p;
                Ss[r * 68 + q + 4 * j] = to_tf32(p);
            }
            s += __shfl_xor_sync(0xffffffffu, s, 1);
            s += __shfl_xor_sync(0xffffffffu, s, 2);
            if (q == 0) {
                float f = __expf(mold - mnew);
                frow[r] = f;
                mrow[r] = mnew;
                lrow[r] = lrow[r] * f + s;
            }
        }
        __syncthreads();

        // ---- rescale O, then O += P @ V : rows [wm*16,+16), hd cols [wn*32,+32) ----
        {
            float f0 = frow[wm * 16 + gid];
            float f8 = frow[wm * 16 + gid + 8];
#pragma unroll
            for (int nf = 0; nf < 4; ++nf) {
                oacc[nf][0] *= f0; oacc[nf][1] *= f0;
                oacc[nf][2] *= f8; oacc[nf][3] *= f8;
            }
        }
#pragma unroll
        for (int ks = 0; ks < 8; ++ks) {
            const int k = ks * 8;
            uint32_t af[4];
            int r = wm * 16;
            af[0] = __float_as_uint(Ss[(r + gid    ) * 68 + k + tig    ]);
            af[1] = __float_as_uint(Ss[(r + gid + 8) * 68 + k + tig    ]);
            af[2] = __float_as_uint(Ss[(r + gid    ) * 68 + k + tig + 4]);
            af[3] = __float_as_uint(Ss[(r + gid + 8) * 68 + k + tig + 4]);
#pragma unroll
            for (int nf = 0; nf < 4; ++nf) {
                int c = wn * 32 + nf * 8;
                uint32_t bf[2];
                // V untransposed: B[k][n] = Vs[kv = k][hd = n], stride 72
                bf[0] = __float_as_uint(Vb[(k + tig    ) * 72 + c + gid]);
                bf[1] = __float_as_uint(Vb[(k + tig + 4) * 72 + c + gid]);
                mma8(oacc[nf], af, bf);
            }
        }
        // no trailing barrier: next iteration's top __syncthreads covers Ss reuse
    }

    // ---- write ctx [B,T,D], tf32-rounded ----
    {
        int r0 = wm * 16 + gid;
        float il0 = 1.f / lrow[r0];
        float il8 = 1.f / lrow[r0 + 8];
        int b = bh >> 5, h = bh & 31;
        size_t base = ((size_t)b * T_ + (size_t)qt * 64) * D_ + h * 64;
#pragma unroll
        for (int nf = 0; nf < 4; ++nf) {
            int col = wn * 32 + nf * 8 + tig * 2;
            float2 v0 = make_float2(to_tf32(oacc[nf][0] * il0), to_tf32(oacc[nf][1] * il0));
            float2 v1 = make_float2(to_tf32(oacc[nf][2] * il8), to_tf32(oacc[nf][3] * il8));
            *(float2*)(ctx + base + (size_t)r0 * D_ + col)       = v0;
            *(float2*)(ctx + base + (size_t)(r0 + 8) * D_ + col) = v1;
        }
    }
}

// ============================================================================
extern "C" void kernel_launch(void* const* d_in, const int* in_sizes, int n_in,
                              void* d_out, int out_size)
{
    (void)in_sizes; (void)n_in; (void)out_size;
    const float* X  = (const float*)d_in[0];
    const float* Wq = (const float*)d_in[1];
    const float* bq = (const float*)d_in[2];
    const float* Wk = (const float*)d_in[3];
    const float* bk = (const float*)d_in[4];
    const float* Wv = (const float*)d_in[5];
    const float* bv = (const float*)d_in[6];
    const float* Wo = (const float*)d_in[7];
    const float* bo = (const float*)d_in[8];
    float* out = (float*)d_out;

    float *x, *wq, *wk, *wv, *wo, *q, *k, *v, *ctx;
    cudaGetSymbolAddress((void**)&x,   g_x);
    cudaGetSymbolAddress((void**)&wq,  g_wq);
    cudaGetSymbolAddress((void**)&wk,  g_wk);
    cudaGetSymbolAddress((void**)&wv,  g_wv);
    cudaGetSymbolAddress((void**)&wo,  g_wo);
    cudaGetSymbolAddress((void**)&q,   g_q);
    cudaGetSymbolAddress((void**)&k,   g_k);
    cudaGetSymbolAddress((void**)&v,   g_v);
    cudaGetSymbolAddress((void**)&ctx, g_ctx);

    cudaFuncSetAttribute(gemm_tf32<0>, cudaFuncAttributeMaxDynamicSharedMemorySize, GEMM_SMEM_BYTES);
    cudaFuncSetAttribute(gemm_tf32<1>, cudaFuncAttributeMaxDynamicSharedMemorySize, GEMM_SMEM_BYTES);
    cudaFuncSetAttribute(attn_flash,   cudaFuncAttributeMaxDynamicSharedMemorySize, ATTN_SMEM_BYTES);

    // pre-round activations + weights to tf32
    const int nx4 = B_ * T_ * D_ / 4;
    const int nw4 = D_ * D_ / 4;
    round_tf32_kernel<<<nx4 / 256, 256>>>((const float4*)X,  (float4*)x,  nx4);
    round_tf32_kernel<<<nw4 / 256, 256>>>((const float4*)Wq, (float4*)wq, nw4);
    round_tf32_kernel<<<nw4 / 256, 256>>>((const float4*)Wk, (float4*)wk, nw4);
    round_tf32_kernel<<<nw4 / 256, 256>>>((const float4*)Wv, (float4*)wv, nw4);
    round_tf32_kernel<<<nw4 / 256, 256>>>((const float4*)Wo, (float4*)wo, nw4);

    const int M = B_ * T_;   // 4096
    const int N = D_;        // 2048
    const int K = D_;        // 2048
    dim3 gg(N / 128, M / 128);   // 16 x 32

    gemm_tf32<1><<<gg, 256, GEMM_SMEM_BYTES>>>(x, wq, bq, q, M, N, K);
    gemm_tf32<1><<<gg, 256, GEMM_SMEM_BYTES>>>(x, wk, bk, k, M, N, K);
    gemm_tf32<1><<<gg, 256, GEMM_SMEM_BYTES>>>(x, wv, bv, v, M, N, K);

    attn_flash<<<dim3(T_ / 64, B_ * H_), 256, ATTN_SMEM_BYTES>>>(q, k, v, ctx);

    gemm_tf32<0><<<gg, 256, GEMM_SMEM_BYTES>>>(ctx, wo, bo, out, M, N, K);
}